// round 12
// baseline (speedup 1.0000x reference)
#include <cuda_runtime.h>
#include <cstdint>

#define NHEAD  16
#define LSEQ   2048
#define DMODEL 1024
#define DHEAD  64
#define NBATCH 2
#define MROWS  (NBATCH * LSEQ)   // 4096
#define NCOLS  (NHEAD * DHEAD)   // 1024

__device__ float g_qp[(size_t)NBATCH * NHEAD * LSEQ * DHEAD];
__device__ float g_kp[(size_t)NBATCH * NHEAD * LSEQ * DHEAD];
__device__ float g_vp[(size_t)NBATCH * NHEAD * LSEQ * DHEAD];
__device__ float g_gate[(size_t)MROWS * NCOLS];
__device__ float g_att[(size_t)MROWS * NCOLS];

__device__ __forceinline__ float tf32r(float x) {
    uint32_t u;
    asm("cvt.rna.tf32.f32 %0, %1;" : "=r"(u) : "f"(x));
    return __uint_as_float(u);
}
__device__ __forceinline__ float ex2(float x) {
    float y;
    asm("ex2.approx.ftz.f32 %0, %1;" : "=f"(y) : "f"(x));
    return y;
}
__device__ __forceinline__ void mma8(float* d,
                                     uint32_t a0, uint32_t a1, uint32_t a2, uint32_t a3,
                                     uint32_t b0, uint32_t b1) {
    asm volatile(
        "mma.sync.aligned.m16n8k8.row.col.f32.tf32.tf32.f32 "
        "{%0,%1,%2,%3}, {%4,%5,%6,%7}, {%8,%9}, {%0,%1,%2,%3};\n"
        : "+f"(d[0]), "+f"(d[1]), "+f"(d[2]), "+f"(d[3])
        : "r"(a0), "r"(a1), "r"(a2), "r"(a3), "r"(b0), "r"(b1));
}
__device__ __forceinline__ void ldsm4(uint32_t* d, uint32_t a) {
    asm volatile("ldmatrix.sync.aligned.m8n8.x4.b16 {%0,%1,%2,%3}, [%4];"
                 : "=r"(d[0]), "=r"(d[1]), "=r"(d[2]), "=r"(d[3]) : "r"(a));
}
__device__ __forceinline__ void cpa16(void* dst, const void* src) {
    uint32_t d = (uint32_t)__cvta_generic_to_shared(dst);
    asm volatile("cp.async.ca.shared.global [%0], [%1], 16;\n" :: "r"(d), "l"(src));
}
#define CP_COMMIT() asm volatile("cp.async.commit_group;\n")
#define CP_WAIT(N)  asm volatile("cp.async.wait_group %0;\n" :: "n"(N))

// ============ GEMM (round-11 config, measured-equal best; unchanged) ============
#define GBM 256
#define GBN 64
#define GBK 16
#define APITCH 20
#define BPITCH 72

__device__ __forceinline__
void gemm_sync_core(const float* __restrict__ X, const float* __restrict__ W,
                    const float* __restrict__ aux, float* __restrict__ out, int mode)
{
    __shared__ float As[GBM * APITCH];
    __shared__ float Bs[GBK * BPITCH];

    const int row0 = blockIdx.y * GBM;
    const int col0 = blockIdx.x * GBN;
    const int tid  = threadIdx.x;
    const int lane = tid & 31, wid = tid >> 5;
    const int g = lane >> 2, t = lane & 3;
    const int warp_m = wid & 3;
    const int warp_n = wid >> 2;

    float acc[4][4][4];
#pragma unroll
    for (int mt = 0; mt < 4; ++mt)
#pragma unroll
        for (int nt = 0; nt < 4; ++nt)
#pragma unroll
            for (int e = 0; e < 4; ++e) acc[mt][nt][e] = 0.f;

    const uint32_t as_u = (uint32_t)__cvta_generic_to_shared(As);
    const uint32_t aoff = as_u +
        ((uint32_t)((warp_m * 64 + ((lane >> 3) & 1) * 8 + (lane & 7)) * APITCH
                    + (lane >> 4) * 4) << 2);
    const int c0 = warp_n * 32 + g;

    for (int k0 = 0; k0 < DMODEL; k0 += GBK) {
#pragma unroll
        for (int i = 0; i < 4; ++i) {
            int idx = tid + i * 256;
            int r = idx >> 2, kq = (idx & 3) * 4;
            float4 v4 = *reinterpret_cast<const float4*>(
                &X[(size_t)(row0 + r) * DMODEL + k0 + kq]);
            float4 w4 = make_float4(tf32r(v4.x), tf32r(v4.y), tf32r(v4.z), tf32r(v4.w));
            *reinterpret_cast<float4*>(&As[r * APITCH + kq]) = w4;
        }
        {
            int kk = tid >> 4, nq = (tid & 15) * 4;
            float4 v4 = *reinterpret_cast<const float4*>(
                &W[(size_t)(k0 + kk) * NCOLS + col0 + nq]);
            float4 w4 = make_float4(tf32r(v4.x), tf32r(v4.y), tf32r(v4.z), tf32r(v4.w));
            *reinterpret_cast<float4*>(&Bs[kk * BPITCH + nq]) = w4;
        }
        __syncthreads();

#pragma unroll
        for (int kc = 0; kc < GBK; kc += 8) {
            uint32_t af[4][4], bf[4][2];
#pragma unroll
            for (int mt = 0; mt < 4; ++mt)
                ldsm4(af[mt], aoff + (uint32_t)((mt * 16 * APITCH + kc) << 2));
#pragma unroll
            for (int nt = 0; nt < 4; ++nt) {
                bf[nt][0] = __float_as_uint(Bs[(kc + t) * BPITCH + c0 + nt * 8]);
                bf[nt][1] = __float_as_uint(Bs[(kc + t + 4) * BPITCH + c0 + nt * 8]);
            }
#pragma unroll
            for (int mt = 0; mt < 4; ++mt)
#pragma unroll
                for (int nt = 0; nt < 4; ++nt)
                    mma8(acc[mt][nt],
                         af[mt][0], af[mt][1], af[mt][2], af[mt][3],
                         bf[nt][0], bf[nt][1]);
        }
        __syncthreads();
    }

#pragma unroll
    for (int mt = 0; mt < 4; ++mt)
#pragma unroll
        for (int nt = 0; nt < 4; ++nt) {
            int rg0 = row0 + warp_m * 64 + mt * 16 + g;
            int cg  = col0 + warp_n * 32 + nt * 8 + 2 * t;
            int rr[4] = {rg0, rg0, rg0 + 8, rg0 + 8};
            int cc[4] = {cg, cg + 1, cg, cg + 1};
#pragma unroll
            for (int e = 0; e < 4; ++e) {
                int row = rr[e], col = cc[e];
                float v = acc[mt][nt][e];
                if (mode <= 2) {
                    if (mode == 0) v *= 0.125f;
                    int bb = row >> 11, l = row & (LSEQ - 1);
                    int hh = col >> 6,  cx = col & (DHEAD - 1);
                    float* dst = (mode == 0) ? g_qp : ((mode == 1) ? g_kp : g_vp);
                    dst[((((size_t)bb * NHEAD + hh) * LSEQ) + l) * DHEAD + cx] = tf32r(v);
                } else if (mode == 3) {
                    float xg = v + aux[col];
                    g_gate[(size_t)row * NCOLS + col] = 1.f / (1.f + __expf(-xg));
                } else {
                    out[(size_t)row * DMODEL + col] = v + aux[col];
                }
            }
        }
}

__global__ __launch_bounds__(256, 2)
void proj4_kernel(const float* __restrict__ Q, const float* __restrict__ K,
                  const float* __restrict__ V,
                  const float* __restrict__ Wq, const float* __restrict__ Wk,
                  const float* __restrict__ Wv, const float* __restrict__ Wg,
                  const float* __restrict__ gbias)
{
    const int z = blockIdx.z;
    const float* X = (z == 1) ? K : ((z == 2) ? V : Q);
    const float* W = (z == 0) ? Wq : ((z == 1) ? Wk : ((z == 2) ? Wv : Wg));
    gemm_sync_core(X, W, gbias, nullptr, z);
}

__global__ __launch_bounds__(256, 2)
void oproj_kernel(const float* __restrict__ Xatt, const float* __restrict__ Wo,
                  const float* __restrict__ obias, float* __restrict__ out)
{
    gemm_sync_core(Xatt, Wo, obias, out, 4);
}

// ===== Flash attention v5: V stored transposed, PV B-fragments via ldmatrix =====
#define QP  68
#define KP  68
#define VTP 68
#define ATTN_SMEM_FLOATS (128*QP + 2*64*KP + 2*64*VTP)   // 26112
#define ATTN_SMEM_BYTES  (ATTN_SMEM_FLOATS * 4)          // 104448

__global__ __launch_bounds__(256, 2)
void attn_kernel(const float* __restrict__ bias, const int* __restrict__ mask)
{
    extern __shared__ float sm[];
    float* q_s   = sm;                     // [128][68]
    float* k_sb  = q_s + 128 * QP;         // 2 x [64][68]  K natural [kk][c]
    float* vt_sb = k_sb + 2 * 64 * KP;     // 2 x [64][68]  V transposed [c][kk]

    const int b = blockIdx.z, h = blockIdx.y;
    const int q0 = blockIdx.x * 128;
    const int tid = threadIdx.x;
    const int lane = tid & 31, wid = tid >> 5;
    const int g = lane >> 2, t = lane & 3;
    const int rw = wid * 16;
    const float L2E = 1.4426950408889634f;

    const float* kbase = g_kp + (((size_t)b * NHEAD + h) * LSEQ) * DHEAD;
    const float* vbase = g_vp + (((size_t)b * NHEAD + h) * LSEQ) * DHEAD;
    const float* qbase = g_qp + (((size_t)b * NHEAD + h) * LSEQ + q0) * DHEAD;

    // Q tile -> smem (async, once)
#pragma unroll
    for (int i = 0; i < 8; ++i) {
        int idx = tid + i * 256;
        int r = idx >> 4, cq = (idx & 15) << 2;
        cpa16(&q_s[r * QP + cq], &qbase[(size_t)r * DHEAD + cq]);
    }
    CP_COMMIT();

    const int kvr = tid >> 2, kvc = (tid & 3) << 2;
    auto issueK = [&](int kt) {
        float* ks = k_sb + (kt & 1) * 64 * KP;
        const float* kb = kbase + (size_t)kt * 64 * DHEAD;
#pragma unroll
        for (int i = 0; i < 4; ++i)
            cpa16(&ks[kvr * KP + kvc + 16 * i], &kb[(size_t)kvr * DHEAD + kvc + 16 * i]);
        CP_COMMIT();
    };
    issueK(0);

    // V tile 0: LDG + transpose store into vt buffer 0
    {
        float* vt = vt_sb;
#pragma unroll
        for (int i = 0; i < 4; ++i) {
            float4 v4 = *reinterpret_cast<const float4*>(
                &vbase[(size_t)kvr * DHEAD + kvc + 16 * i]);
            int c = kvc + 16 * i;
            vt[(c + 0) * VTP + kvr] = v4.x;
            vt[(c + 1) * VTP + kvr] = v4.y;
            vt[(c + 2) * VTP + kvr] = v4.z;
            vt[(c + 3) * VTP + kvr] = v4.w;
        }
    }

    // ldmatrix per-lane offsets (b16 view of f32: lane -> (row l>>2, fcol l&3))
    const int i8 = lane & 7;
    const uint32_t smem_u = (uint32_t)__cvta_generic_to_shared(sm);
    const uint32_t qoff = smem_u +
        ((uint32_t)((rw + ((lane >> 3) & 1) * 8 + i8) * QP + (lane >> 4) * 4) << 2);
    // shared quadrant pattern for K and VT (identical pitch 68):
    const uint32_t nkoff = (uint32_t)(((lane >> 4) * 8 + i8) * KP
                                      + ((lane >> 3) & 1) * 4) << 2;
    const uint32_t k_u  = smem_u + (uint32_t)(128 * QP) * 4u;
    const uint32_t vt_u = smem_u + (uint32_t)(128 * QP + 2 * 64 * KP) * 4u;

    float acc[8][4];
#pragma unroll
    for (int nt = 0; nt < 8; ++nt)
#pragma unroll
        for (int e = 0; e < 4; ++e) acc[nt][e] = 0.f;
    float mA = -1e30f, mB = -1e30f, lA = 0.f, lB = 0.f;

    const size_t rowA = ((size_t)b * NHEAD + h) * LSEQ + q0 + rw + g;
    const size_t rowB = rowA + 8;
    const int srcA = (lane & ~3) | (t >> 1);
    const int srcB = srcA + 2;

    for (int kt = 0; kt < LSEQ / 64; ++kt) {
        CP_WAIT(0);
        __syncthreads();               // K[kt] + VT[kt&1] visible; prior buffers free
        if (kt + 1 < LSEQ / 64) issueK(kt + 1);

        const int k0 = kt * 64;

        // bias prefetch (latency hidden under S-gemm)
        float2 bA[8], bB[8];
        {
            const float* bAp = bias + rowA * (size_t)LSEQ + k0 + 2 * t;
            const float* bBp = bias + rowB * (size_t)LSEQ + k0 + 2 * t;
#pragma unroll
            for (int nt = 0; nt < 8; ++nt) {
                bA[nt] = __ldcs(reinterpret_cast<const float2*>(bAp + nt * 8));
                bB[nt] = __ldcs(reinterpret_cast<const float2*>(bBp + nt * 8));
            }
        }

        const uint32_t kb_u = k_u + (uint32_t)((kt & 1) * 64 * KP) * 4u + nkoff;

        // ---- S = q * k^T via ldmatrix ----
        float sacc[8][4];
#pragma unroll
        for (int nt = 0; nt < 8; ++nt)
#pragma unroll
            for (int e = 0; e < 4; ++e) sacc[nt][e] = 0.f;
#pragma unroll
        for (int j = 0; j < 8; ++j) {
            uint32_t af[4];
            ldsm4(af, qoff + (j << 5));
#pragma unroll
            for (int ntp = 0; ntp < 4; ++ntp) {
                uint32_t bf[4];
                ldsm4(bf, kb_u + (uint32_t)(ntp * 16 * KP) * 4u + (j << 5));
                mma8(sacc[2 * ntp],     af[0], af[1], af[2], af[3], bf[0], bf[1]);
                mma8(sacc[2 * ntp + 1], af[0], af[1], af[2], af[3], bf[2], bf[3]);
            }
        }

        // ---- mask + bias fold ----
        uint32_t mbits = 0;
        {
            const int* mAp = mask + rowA * (size_t)LSEQ + k0 + 2 * t;
            const int* mBp = mask + rowB * (size_t)LSEQ + k0 + 2 * t;
#pragma unroll
            for (int nt = 0; nt < 8; ++nt) {
                int2 ma = __ldcs(reinterpret_cast<const int2*>(mAp + nt * 8));
                int2 mc = __ldcs(reinterpret_cast<const int2*>(mBp + nt * 8));
                sacc[nt][0] += bA[nt].x;  sacc[nt][1] += bA[nt].y;
                sacc[nt][2] += bB[nt].x;  sacc[nt][3] += bB[nt].y;
                mbits |= (ma.x ? 1u : 0u) << (nt * 4)
                       | (ma.y ? 1u : 0u) << (nt * 4 + 1)
                       | (mc.x ? 1u : 0u) << (nt * 4 + 2)
                       | (mc.y ? 1u : 0u) << (nt * 4 + 3);
            }
        }

        // ---- online softmax in registers ----
        float mxA = -1e30f, mxB = -1e30f;
#pragma unroll
        for (int nt = 0; nt < 8; ++nt) {
            mxA = fmaxf(mxA, fmaxf(sacc[nt][0], sacc[nt][1]));
            mxB = fmaxf(mxB, fmaxf(sacc[nt][2], sacc[nt][3]));
        }
        mxA = fmaxf(mxA, __shfl_xor_sync(0xffffffffu, mxA, 1));
        mxA = fmaxf(mxA, __shfl_xor_sync(0xffffffffu, mxA, 2));
        mxB = fmaxf(mxB, __shfl_xor_sync(0xffffffffu, mxB, 1));
        mxB = fmaxf(mxB, __shfl_xor_sync(0xffffffffu, mxB, 2));
        float mnA = fmaxf(mA, mxA), mnB = fmaxf(mB, mxB);
        float alA = ex2((mA - mnA) * L2E), alB = ex2((mB - mnB) * L2E);
        mA = mnA; mB = mnB;

        float lsA = 0.f, lsB = 0.f;
#pragma unroll
        for (int nt = 0; nt < 8; ++nt) {
            float p0 = ex2((sacc[nt][0] - mnA) * L2E);
            float p1 = ex2((sacc[nt][1] - mnA) * L2E);
            float p2 = ex2((sacc[nt][2] - mnB) * L2E);
            float p3 = ex2((sacc[nt][3] - mnB) * L2E);
            lsA += p0 + p1;  lsB += p2 + p3;               // denom: ALL entries
            sacc[nt][0] = tf32r(((mbits >> (nt * 4    )) & 1u) ? p0 : 0.f);
            sacc[nt][1] = tf32r(((mbits >> (nt * 4 + 1)) & 1u) ? p1 : 0.f);
            sacc[nt][2] = tf32r(((mbits >> (nt * 4 + 2)) & 1u) ? p2 : 0.f);
            sacc[nt][3] = tf32r(((mbits >> (nt * 4 + 3)) & 1u) ? p3 : 0.f);
        }
        lsA += __shfl_xor_sync(0xffffffffu, lsA, 1);
        lsA += __shfl_xor_sync(0xffffffffu, lsA, 2);
        lsB += __shfl_xor_sync(0xffffffffu, lsB, 1);
        lsB += __shfl_xor_sync(0xffffffffu, lsB, 2);
        lA = lA * alA + lsA;  lB = lB * alB + lsB;

        // ---- V[kt+1] LDG (latency hidden under PV) ----
        float4 vv[4];
        if (kt + 1 < LSEQ / 64) {
            const float* vb = vbase + (size_t)(kt + 1) * 64 * DHEAD;
#pragma unroll
            for (int i = 0; i < 4; ++i)
                vv[i] = *reinterpret_cast<const float4*>(
                    &vb[(size_t)kvr * DHEAD + kvc + 16 * i]);
        }

        // ---- rescale acc; PV with inline permute + ldmatrix V fragments ----
#pragma unroll
        for (int nt = 0; nt < 8; ++nt) {
            acc[nt][0] *= alA; acc[nt][1] *= alA;
            acc[nt][2] *= alB; acc[nt][3] *= alB;
        }
        const uint32_t vb_u = vt_u + (uint32_t)((kt & 1) * 64 * VTP) * 4u + nkoff;
#pragma unroll
        for (int j = 0; j < 8; ++j) {
            float c0 = sacc[j][0], c1 = sacc[j][1], c2 = sacc[j][2], c3 = sacc[j][3];
            float v0 = __shfl_sync(0xffffffffu, c0, srcA);
            float v1 = __shfl_sync(0xffffffffu, c1, srcA);
            float v2 = __shfl_sync(0xffffffffu, c0, srcB);
            float v3 = __shfl_sync(0xffffffffu, c1, srcB);
            float w0 = __shfl_sync(0xffffffffu, c2, srcA);
            float w1 = __shfl_sync(0xffffffffu, c3, srcA);
            float w2 = __shfl_sync(0xffffffffu, c2, srcB);
            float w3 = __shfl_sync(0xffffffffu, c3, srcB);
            uint32_t pa0 = __float_as_uint((t & 1) ? v1 : v0);
            uint32_t pa1 = __float_as_uint((t & 1) ? w1 : w0);
            uint32_t pa2 = __float_as_uint((t & 1) ? v3 : v2);
            uint32_t pa3 = __float_as_uint((t & 1) ? w3 : w2);
#pragma unroll
            for (int ntp = 0; ntp < 4; ++ntp) {
                uint32_t bf[4];
                ldsm4(bf, vb_u + (uint32_t)(ntp * 16 * VTP) * 4u + (j << 5));
                mma8(acc[2 * ntp],     pa0, pa1, pa2, pa3, bf[0], bf[1]);
                mma8(acc[2 * ntp + 1], pa0, pa1, pa2, pa3, bf[2], bf[3]);
            }
        }

        // ---- V[kt+1] transpose store into the other buffer ----
        if (kt + 1 < LSEQ / 64) {
            float* vt = vt_sb + ((kt + 1) & 1) * 64 * VTP;
#pragma unroll
            for (int i = 0; i < 4; ++i) {
                int c = kvc + 16 * i;
                vt[(c + 0) * VTP + kvr] = vv[i].x;
                vt[(c + 1) * VTP + kvr] = vv[i].y;
                vt[(c + 2) * VTP + kvr] = vv[i].z;
                vt[(c + 3) * VTP + kvr] = vv[i].w;
            }
        }
    }

    // ---- epilogue: /l, *gate ----
    float invA = 1.f / lA, invB = 1.f / lB;
    size_t gRowA = (size_t)b * LSEQ + q0 + rw + g;
    size_t gRowB = gRowA + 8;
#pragma unroll
    for (int nt = 0; nt < 8; ++nt) {
        size_t iA = gRowA * NCOLS + h * DHEAD + nt * 8 + 2 * t;
        size_t iB = gRowB * NCOLS + h * DHEAD + nt * 8 + 2 * t;
        float2 gA = *reinterpret_cast<const float2*>(&g_gate[iA]);
        float2 gB = *reinterpret_cast<const float2*>(&g_gate[iB]);
        float2 oA = { acc[nt][0] * invA * gA.x, acc[nt][1] * invA * gA.y };
        float2 oB = { acc[nt][2] * invB * gB.x, acc[nt][3] * invB * gB.y };
        *reinterpret_cast<float2*>(&g_att[iA]) = oA;
        *reinterpret_cast<float2*>(&g_att[iB]) = oB;
    }
}

// ===== launcher =====
extern "C" void kernel_launch(void* const* d_in, const int* in_sizes, int n_in,
                              void* d_out, int out_size)
{
    const float* Q    = (const float*)d_in[0];
    const float* K    = (const float*)d_in[1];
    const float* V    = (const float*)d_in[2];
    const float* bias = (const float*)d_in[3];
    const int*   mask = (const int*)d_in[4];
    const float* qw   = (const float*)d_in[5];
    const float* kw   = (const float*)d_in[6];
    const float* vw   = (const float*)d_in[7];
    const float* gw   = (const float*)d_in[8];
    const float* gb   = (const float*)d_in[9];
    const float* ow   = (const float*)d_in[10];
    const float* ob   = (const float*)d_in[11];
    float* out = (float*)d_out;

    static float* g_att_p = nullptr;
    if (!g_att_p) cudaGetSymbolAddress((void**)&g_att_p, g_att);

    cudaFuncSetAttribute(attn_kernel, cudaFuncAttributeMaxDynamicSharedMemorySize,
                         ATTN_SMEM_BYTES);

    dim3 gp(NCOLS / GBN, MROWS / GBM, 4);      // 16 x 16 x 4 = 1024 blocks
    proj4_kernel<<<gp, 256>>>(Q, K, V, qw, kw, vw, gw, gb);

    dim3 ga(LSEQ / 128, NHEAD, NBATCH);        // 16 x 16 x 2
    attn_kernel<<<ga, 256, ATTN_SMEM_BYTES>>>(bias, mask);

    dim3 go(DMODEL / GBN, MROWS / GBM, 1);     // 16 x 16
    oproj_kernel<<<go, 256>>>(g_att_p, ow, ob, out);
}

// round 16
// speedup vs baseline: 1.0859x; 1.0859x over previous
#include <cuda_runtime.h>
#include <cstdint>

#define NHEAD  16
#define LSEQ   2048
#define DMODEL 1024
#define DHEAD  64
#define NBATCH 2
#define MROWS  (NBATCH * LSEQ)   // 4096
#define NCOLS  (NHEAD * DHEAD)   // 1024

__device__ float g_qp[(size_t)NBATCH * NHEAD * LSEQ * DHEAD];
__device__ float g_kp[(size_t)NBATCH * NHEAD * LSEQ * DHEAD];
__device__ float g_vp[(size_t)NBATCH * NHEAD * LSEQ * DHEAD];
__device__ float g_gate[(size_t)MROWS * NCOLS];
__device__ float g_att[(size_t)MROWS * NCOLS];

__device__ __forceinline__ float tf32r(float x) {
    uint32_t u;
    asm("cvt.rna.tf32.f32 %0, %1;" : "=r"(u) : "f"(x));
    return __uint_as_float(u);
}
__device__ __forceinline__ uint32_t tf32u(uint32_t x) {
    uint32_t u;
    asm("cvt.rna.tf32.f32 %0, %1;" : "=r"(u) : "r"(x));
    return u;
}
__device__ __forceinline__ float ex2(float x) {
    float y;
    asm("ex2.approx.ftz.f32 %0, %1;" : "=f"(y) : "f"(x));
    return y;
}
__device__ __forceinline__ void mma8(float* d,
                                     uint32_t a0, uint32_t a1, uint32_t a2, uint32_t a3,
                                     uint32_t b0, uint32_t b1) {
    asm volatile(
        "mma.sync.aligned.m16n8k8.row.col.f32.tf32.tf32.f32 "
        "{%0,%1,%2,%3}, {%4,%5,%6,%7}, {%8,%9}, {%0,%1,%2,%3};\n"
        : "+f"(d[0]), "+f"(d[1]), "+f"(d[2]), "+f"(d[3])
        : "r"(a0), "r"(a1), "r"(a2), "r"(a3), "r"(b0), "r"(b1));
}
__device__ __forceinline__ void ldsm4(uint32_t* d, uint32_t a) {
    asm volatile("ldmatrix.sync.aligned.m8n8.x4.b16 {%0,%1,%2,%3}, [%4];"
                 : "=r"(d[0]), "=r"(d[1]), "=r"(d[2]), "=r"(d[3]) : "r"(a));
}
__device__ __forceinline__ void cpa16(void* dst, const void* src) {
    uint32_t d = (uint32_t)__cvta_generic_to_shared(dst);
    asm volatile("cp.async.ca.shared.global [%0], [%1], 16;\n" :: "r"(d), "l"(src));
}
#define CP_COMMIT() asm volatile("cp.async.commit_group;\n")
#define CP_WAIT(N)  asm volatile("cp.async.wait_group %0;\n" :: "n"(N))

// ========== GEMM (round-9 core, GBK 16->32: half the barriers) ==========
#define GBM 128
#define GBN 64
#define GBK 32
#define APITCH 36   // 144B rows, 16B-aligned; ldsm phase 9r%8=r%8 distinct
#define BPITCH 72   // B fragment banks 8t+g all distinct

__device__ __forceinline__
void gemm_sync_core(const float* __restrict__ X, const float* __restrict__ W,
                    const float* __restrict__ aux, float* __restrict__ out, int mode)
{
    __shared__ float As[GBM * APITCH];   // 18.4 KB
    __shared__ float Bs[GBK * BPITCH];   // 9.2 KB

    const int row0 = blockIdx.y * GBM;
    const int col0 = blockIdx.x * GBN;
    const int tid  = threadIdx.x;
    const int lane = tid & 31, wid = tid >> 5;
    const int g = lane >> 2, t = lane & 3;
    const int warp_m = wid & 3, warp_n = wid >> 2;   // 32x32 warp tiles

    float acc[2][4][4];
#pragma unroll
    for (int mt = 0; mt < 2; ++mt)
#pragma unroll
        for (int nt = 0; nt < 4; ++nt)
#pragma unroll
            for (int e = 0; e < 4; ++e) acc[mt][nt][e] = 0.f;

    const uint32_t as_u = (uint32_t)__cvta_generic_to_shared(As);
    const uint32_t aoff = as_u +
        ((uint32_t)((warp_m * 32 + ((lane >> 3) & 1) * 8 + (lane & 7)) * APITCH
                    + (lane >> 4) * 4) << 2);
    const int c0 = warp_n * 32 + g;

    for (int k0 = 0; k0 < DMODEL; k0 += GBK) {
        // A tile 128x32: 4 float4/thread, raw store (cvt fragment-side)
#pragma unroll
        for (int i = 0; i < 4; ++i) {
            int idx = tid + i * 256;
            int r = idx >> 3, kq = (idx & 7) * 4;
            float4 v4 = *reinterpret_cast<const float4*>(
                &X[(size_t)(row0 + r) * DMODEL + k0 + kq]);
            *reinterpret_cast<float4*>(&As[r * APITCH + kq]) = v4;
        }
        // B tile 32x64: 2 float4/thread, store-side cvt
#pragma unroll
        for (int i = 0; i < 2; ++i) {
            int idx = tid + i * 256;
            int kk = idx >> 4, nq = (idx & 15) * 4;
            float4 v4 = *reinterpret_cast<const float4*>(
                &W[(size_t)(k0 + kk) * NCOLS + col0 + nq]);
            float4 w4 = make_float4(tf32r(v4.x), tf32r(v4.y), tf32r(v4.z), tf32r(v4.w));
            *reinterpret_cast<float4*>(&Bs[kk * BPITCH + nq]) = w4;
        }
        __syncthreads();

#pragma unroll
        for (int kc = 0; kc < GBK; kc += 8) {
            uint32_t af[2][4], bf[4][2];
#pragma unroll
            for (int mt = 0; mt < 2; ++mt) {
                ldsm4(af[mt], aoff + (uint32_t)((mt * 16 * APITCH + kc) << 2));
                af[mt][0] = tf32u(af[mt][0]); af[mt][1] = tf32u(af[mt][1]);
                af[mt][2] = tf32u(af[mt][2]); af[mt][3] = tf32u(af[mt][3]);
            }
#pragma unroll
            for (int nt = 0; nt < 4; ++nt) {
                bf[nt][0] = __float_as_uint(Bs[(kc + t) * BPITCH + c0 + nt * 8]);
                bf[nt][1] = __float_as_uint(Bs[(kc + t + 4) * BPITCH + c0 + nt * 8]);
            }
#pragma unroll
            for (int mt = 0; mt < 2; ++mt)
#pragma unroll
                for (int nt = 0; nt < 4; ++nt)
                    mma8(acc[mt][nt],
                         af[mt][0], af[mt][1], af[mt][2], af[mt][3],
                         bf[nt][0], bf[nt][1]);
        }
        __syncthreads();
    }

#pragma unroll
    for (int mt = 0; mt < 2; ++mt)
#pragma unroll
        for (int nt = 0; nt < 4; ++nt) {
            int rg0 = row0 + warp_m * 32 + mt * 16 + g;
            int cg  = col0 + warp_n * 32 + nt * 8 + 2 * t;
            int rr[4] = {rg0, rg0, rg0 + 8, rg0 + 8};
            int cc[4] = {cg, cg + 1, cg, cg + 1};
#pragma unroll
            for (int e = 0; e < 4; ++e) {
                int row = rr[e], col = cc[e];
                float v = acc[mt][nt][e];
                if (mode <= 2) {
                    if (mode == 0) v *= 0.125f;
                    int bb = row >> 11, l = row & (LSEQ - 1);
                    int hh = col >> 6,  cx = col & (DHEAD - 1);
                    float* dst = (mode == 0) ? g_qp : ((mode == 1) ? g_kp : g_vp);
                    dst[((((size_t)bb * NHEAD + hh) * LSEQ) + l) * DHEAD + cx] = tf32r(v);
                } else if (mode == 3) {
                    float xg = v + aux[col];
                    g_gate[(size_t)row * NCOLS + col] = 1.f / (1.f + __expf(-xg));
                } else {
                    out[(size_t)row * DMODEL + col] = v + aux[col];
                }
            }
        }
}

__global__ __launch_bounds__(256)
void proj4_kernel(const float* __restrict__ Q, const float* __restrict__ K,
                  const float* __restrict__ V,
                  const float* __restrict__ Wq, const float* __restrict__ Wk,
                  const float* __restrict__ Wv, const float* __restrict__ Wg,
                  const float* __restrict__ gbias)
{
    const int z = blockIdx.z;
    const float* X = (z == 1) ? K : ((z == 2) ? V : Q);
    const float* W = (z == 0) ? Wq : ((z == 1) ? Wk : ((z == 2) ? Wv : Wg));
    gemm_sync_core(X, W, gbias, nullptr, z);
}

__global__ __launch_bounds__(256)
void oproj_kernel(const float* __restrict__ Xatt, const float* __restrict__ Wo,
                  const float* __restrict__ obias, float* __restrict__ out)
{
    gemm_sync_core(Xatt, Wo, obias, out, 4);
}

// ===== Flash attention (round-8/9 winner, reverted & verbatim) =====
#define QP 68
#define KP 68
#define VP 72
#define ATTN_SMEM_FLOATS (128*QP + 2*64*KP + 2*64*VP)   // 26624
#define ATTN_SMEM_BYTES  (ATTN_SMEM_FLOATS * 4)         // 106496

__global__ __launch_bounds__(256, 2)
void attn_kernel(const float* __restrict__ bias, const int* __restrict__ mask)
{
    extern __shared__ float sm[];
    float* q_s  = sm;                    // [128][68]
    float* k_sb = q_s + 128 * QP;        // 2 x [64][68]
    float* v_sb = k_sb + 2 * 64 * KP;    // 2 x [64][72]

    const int b = blockIdx.z, h = blockIdx.y;
    const int q0 = blockIdx.x * 128;
    const int tid = threadIdx.x;
    const int lane = tid & 31, wid = tid >> 5;
    const int g = lane >> 2, t = lane & 3;
    const int rw = wid * 16;
    const float L2E = 1.4426950408889634f;

    const float* kbase = g_kp + (((size_t)b * NHEAD + h) * LSEQ) * DHEAD;
    const float* vbase = g_vp + (((size_t)b * NHEAD + h) * LSEQ) * DHEAD;
    const float* qbase = g_qp + (((size_t)b * NHEAD + h) * LSEQ + q0) * DHEAD;

#pragma unroll
    for (int i = 0; i < 8; ++i) {
        int idx = tid + i * 256;
        int r = idx >> 4, cq = (idx & 15) << 2;
        cpa16(&q_s[r * QP + cq], &qbase[(size_t)r * DHEAD + cq]);
    }
    CP_COMMIT();

    const int kvr = tid >> 2, kvc = (tid & 3) << 2;
    auto issue = [&](int kt) {
        float* ks = k_sb + (kt & 1) * 64 * KP;
        float* vs = v_sb + (kt & 1) * 64 * VP;
        const float* kb = kbase + (size_t)kt * 64 * DHEAD;
        const float* vb = vbase + (size_t)kt * 64 * DHEAD;
#pragma unroll
        for (int i = 0; i < 4; ++i) {
            cpa16(&ks[kvr * KP + kvc + 16 * i], &kb[(size_t)kvr * DHEAD + kvc + 16 * i]);
            cpa16(&vs[kvr * VP + kvc + 16 * i], &vb[(size_t)kvr * DHEAD + kvc + 16 * i]);
        }
        CP_COMMIT();
    };
    issue(0);

    const int i8 = lane & 7;
    const uint32_t smem_u = (uint32_t)__cvta_generic_to_shared(sm);
    const uint32_t qoff = smem_u +
        ((uint32_t)((rw + ((lane >> 3) & 1) * 8 + i8) * QP + (lane >> 4) * 4) << 2);
    const uint32_t koff = (uint32_t)(((lane >> 4) * 8 + i8) * KP
                                     + ((lane >> 3) & 1) * 4) << 2;
    const uint32_t k_u = smem_u + (uint32_t)(128 * QP) * 4u;

    float acc[8][4];
#pragma unroll
    for (int nt = 0; nt < 8; ++nt)
#pragma unroll
        for (int e = 0; e < 4; ++e) acc[nt][e] = 0.f;
    float mA = -1e30f, mB = -1e30f, lA = 0.f, lB = 0.f;

    const size_t rowA = ((size_t)b * NHEAD + h) * LSEQ + q0 + rw + g;
    const size_t rowB = rowA + 8;
    const int srcA = (lane & ~3) | (t >> 1);
    const int srcB = srcA + 2;

    for (int kt = 0; kt < LSEQ / 64; ++kt) {
        CP_WAIT(0);
        __syncthreads();
        if (kt + 1 < LSEQ / 64) issue(kt + 1);

        const int k0 = kt * 64;

        float2 bA[8], bB[8];
        {
            const float* bAp = bias + rowA * (size_t)LSEQ + k0 + 2 * t;
            const float* bBp = bias + rowB * (size_t)LSEQ + k0 + 2 * t;
#pragma unroll
            for (int nt = 0; nt < 8; ++nt) {
                bA[nt] = __ldcs(reinterpret_cast<const float2*>(bAp + nt * 8));
                bB[nt] = __ldcs(reinterpret_cast<const float2*>(bBp + nt * 8));
            }
        }

        const uint32_t kb_u = k_u + (uint32_t)((kt & 1) * 64 * KP) * 4u + koff;
        const float* vs = v_sb + (kt & 1) * 64 * VP;

        float sacc[8][4];
#pragma unroll
        for (int nt = 0; nt < 8; ++nt)
#pragma unroll
            for (int e = 0; e < 4; ++e) sacc[nt][e] = 0.f;
#pragma unroll
        for (int j = 0; j < 8; ++j) {
            uint32_t af[4];
            ldsm4(af, qoff + (j << 5));
#pragma unroll
            for (int ntp = 0; ntp < 4; ++ntp) {
                uint32_t bf[4];
                ldsm4(bf, kb_u + (uint32_t)(ntp * 16 * KP) * 4u + (j << 5));
                mma8(sacc[2 * ntp],     af[0], af[1], af[2], af[3], bf[0], bf[1]);
                mma8(sacc[2 * ntp + 1], af[0], af[1], af[2], af[3], bf[2], bf[3]);
            }
        }

        uint32_t mbits = 0;
        {
            const int* mAp = mask + rowA * (size_t)LSEQ + k0 + 2 * t;
            const int* mBp = mask + rowB * (size_t)LSEQ + k0 + 2 * t;
#pragma unroll
            for (int nt = 0; nt < 8; ++nt) {
                int2 ma = __ldcs(reinterpret_cast<const int2*>(mAp + nt * 8));
                int2 mc = __ldcs(reinterpret_cast<const int2*>(mBp + nt * 8));
                sacc[nt][0] += bA[nt].x;  sacc[nt][1] += bA[nt].y;
                sacc[nt][2] += bB[nt].x;  sacc[nt][3] += bB[nt].y;
                mbits |= (ma.x ? 1u : 0u) << (nt * 4)
                       | (ma.y ? 1u : 0u) << (nt * 4 + 1)
                       | (mc.x ? 1u : 0u) << (nt * 4 + 2)
                       | (mc.y ? 1u : 0u) << (nt * 4 + 3);
            }
        }

        float mxA = -1e30f, mxB = -1e30f;
#pragma unroll
        for (int nt = 0; nt < 8; ++nt) {
            mxA = fmaxf(mxA, fmaxf(sacc[nt][0], sacc[nt][1]));
            mxB = fmaxf(mxB, fmaxf(sacc[nt][2], sacc[nt][3]));
        }
        mxA = fmaxf(mxA, __shfl_xor_sync(0xffffffffu, mxA, 1));
        mxA = fmaxf(mxA, __shfl_xor_sync(0xffffffffu, mxA, 2));
        mxB = fmaxf(mxB, __shfl_xor_sync(0xffffffffu, mxB, 1));
        mxB = fmaxf(mxB, __shfl_xor_sync(0xffffffffu, mxB, 2));
        float mnA = fmaxf(mA, mxA), mnB = fmaxf(mB, mxB);
        float alA = ex2((mA - mnA) * L2E), alB = ex2((mB - mnB) * L2E);
        mA = mnA; mB = mnB;

        float lsA = 0.f, lsB = 0.f;
#pragma unroll
        for (int nt = 0; nt < 8; ++nt) {
            float p0 = ex2((sacc[nt][0] - mnA) * L2E);
            float p1 = ex2((sacc[nt][1] - mnA) * L2E);
            float p2 = ex2((sacc[nt][2] - mnB) * L2E);
            float p3 = ex2((sacc[nt][3] - mnB) * L2E);
            lsA += p0 + p1;  lsB += p2 + p3;               // denom: ALL entries
            sacc[nt][0] = tf32r(((mbits >> (nt * 4    )) & 1u) ? p0 : 0.f);
            sacc[nt][1] = tf32r(((mbits >> (nt * 4 + 1)) & 1u) ? p1 : 0.f);
            sacc[nt][2] = tf32r(((mbits >> (nt * 4 + 2)) & 1u) ? p2 : 0.f);
            sacc[nt][3] = tf32r(((mbits >> (nt * 4 + 3)) & 1u) ? p3 : 0.f);
        }
        lsA += __shfl_xor_sync(0xffffffffu, lsA, 1);
        lsA += __shfl_xor_sync(0xffffffffu, lsA, 2);
        lsB += __shfl_xor_sync(0xffffffffu, lsB, 1);
        lsB += __shfl_xor_sync(0xffffffffu, lsB, 2);
        lA = lA * alA + lsA;  lB = lB * alB + lsB;

#pragma unroll
        for (int nt = 0; nt < 8; ++nt) {
            acc[nt][0] *= alA; acc[nt][1] *= alA;
            acc[nt][2] *= alB; acc[nt][3] *= alB;
        }
#pragma unroll
        for (int j = 0; j < 8; ++j) {
            float c0 = sacc[j][0], c1 = sacc[j][1], c2 = sacc[j][2], c3 = sacc[j][3];
            float v0 = __shfl_sync(0xffffffffu, c0, srcA);
            float v1 = __shfl_sync(0xffffffffu, c1, srcA);
            float v2 = __shfl_sync(0xffffffffu, c0, srcB);
            float v3 = __shfl_sync(0xffffffffu, c1, srcB);
            float w0 = __shfl_sync(0xffffffffu, c2, srcA);
            float w1 = __shfl_sync(0xffffffffu, c3, srcA);
            float w2 = __shfl_sync(0xffffffffu, c2, srcB);
            float w3 = __shfl_sync(0xffffffffu, c3, srcB);
            uint32_t pa0 = __float_as_uint((t & 1) ? v1 : v0);
            uint32_t pa1 = __float_as_uint((t & 1) ? w1 : w0);
            uint32_t pa2 = __float_as_uint((t & 1) ? v3 : v2);
            uint32_t pa3 = __float_as_uint((t & 1) ? w3 : w2);
#pragma unroll
            for (int nt = 0; nt < 8; ++nt) {
                uint32_t b0 = __float_as_uint(vs[(j * 8 + t) * VP + nt * 8 + g]);
                uint32_t b1 = __float_as_uint(vs[(j * 8 + t + 4) * VP + nt * 8 + g]);
                mma8(acc[nt], pa0, pa1, pa2, pa3, b0, b1);
            }
        }
    }

    float invA = 1.f / lA, invB = 1.f / lB;
    size_t gRowA = (size_t)b * LSEQ + q0 + rw + g;
    size_t gRowB = gRowA + 8;
#pragma unroll
    for (int nt = 0; nt < 8; ++nt) {
        size_t iA = gRowA * NCOLS + h * DHEAD + nt * 8 + 2 * t;
        size_t iB = gRowB * NCOLS + h * DHEAD + nt * 8 + 2 * t;
        float2 gA = *reinterpret_cast<const float2*>(&g_gate[iA]);
        float2 gB = *reinterpret_cast<const float2*>(&g_gate[iB]);
        float2 oA = { acc[nt][0] * invA * gA.x, acc[nt][1] * invA * gA.y };
        float2 oB = { acc[nt][2] * invB * gB.x, acc[nt][3] * invB * gB.y };
        *reinterpret_cast<float2*>(&g_att[iA]) = oA;
        *reinterpret_cast<float2*>(&g_att[iB]) = oB;
    }
}

// ===== launcher =====
extern "C" void kernel_launch(void* const* d_in, const int* in_sizes, int n_in,
                              void* d_out, int out_size)
{
    const float* Q    = (const float*)d_in[0];
    const float* K    = (const float*)d_in[1];
    const float* V    = (const float*)d_in[2];
    const float* bias = (const float*)d_in[3];
    const int*   mask = (const int*)d_in[4];
    const float* qw   = (const float*)d_in[5];
    const float* kw   = (const float*)d_in[6];
    const float* vw   = (const float*)d_in[7];
    const float* gw   = (const float*)d_in[8];
    const float* gb   = (const float*)d_in[9];
    const float* ow   = (const float*)d_in[10];
    const float* ob   = (const float*)d_in[11];
    float* out = (float*)d_out;

    static float* g_att_p = nullptr;
    if (!g_att_p) cudaGetSymbolAddress((void**)&g_att_p, g_att);

    cudaFuncSetAttribute(attn_kernel, cudaFuncAttributeMaxDynamicSharedMemorySize,
                         ATTN_SMEM_BYTES);

    dim3 gp(NCOLS / GBN, MROWS / GBM, 4);      // 16 x 32 x 4 = 2048 blocks
    proj4_kernel<<<gp, 256>>>(Q, K, V, qw, kw, vw, gw, gb);

    dim3 ga(LSEQ / 128, NHEAD, NBATCH);        // 16 x 16 x 2
    attn_kernel<<<ga, 256, ATTN_SMEM_BYTES>>>(bias, mask);

    dim3 go(DMODEL / GBN, MROWS / GBM, 1);     // 16 x 32
    oproj_kernel<<<go, 256>>>(g_att_p, ow, ob, out);
}

// round 17
// speedup vs baseline: 1.3221x; 1.2174x over previous
#include <cuda_runtime.h>
#include <cstdint>

#define NHEAD  16
#define LSEQ   2048
#define DMODEL 1024
#define DHEAD  64
#define NBATCH 2
#define MROWS  (NBATCH * LSEQ)   // 4096
#define NCOLS  (NHEAD * DHEAD)   // 1024

__device__ float g_qp[(size_t)NBATCH * NHEAD * LSEQ * DHEAD];
__device__ float g_kp[(size_t)NBATCH * NHEAD * LSEQ * DHEAD];
__device__ float g_vp[(size_t)NBATCH * NHEAD * LSEQ * DHEAD];
__device__ float g_gate[(size_t)MROWS * NCOLS];
__device__ float g_att[(size_t)MROWS * NCOLS];

__device__ __forceinline__ float tf32r(float x) {
    uint32_t u;
    asm("cvt.rna.tf32.f32 %0, %1;" : "=r"(u) : "f"(x));
    return __uint_as_float(u);
}
__device__ __forceinline__ uint32_t tf32u(uint32_t x) {
    uint32_t u;
    asm("cvt.rna.tf32.f32 %0, %1;" : "=r"(u) : "r"(x));
    return u;
}
__device__ __forceinline__ float ex2(float x) {
    float y;
    asm("ex2.approx.ftz.f32 %0, %1;" : "=f"(y) : "f"(x));
    return y;
}
__device__ __forceinline__ void mma8(float* d,
                                     uint32_t a0, uint32_t a1, uint32_t a2, uint32_t a3,
                                     uint32_t b0, uint32_t b1) {
    asm volatile(
        "mma.sync.aligned.m16n8k8.row.col.f32.tf32.tf32.f32 "
        "{%0,%1,%2,%3}, {%4,%5,%6,%7}, {%8,%9}, {%0,%1,%2,%3};\n"
        : "+f"(d[0]), "+f"(d[1]), "+f"(d[2]), "+f"(d[3])
        : "r"(a0), "r"(a1), "r"(a2), "r"(a3), "r"(b0), "r"(b1));
}
__device__ __forceinline__ void ldsm4(uint32_t* d, uint32_t a) {
    asm volatile("ldmatrix.sync.aligned.m8n8.x4.b16 {%0,%1,%2,%3}, [%4];"
                 : "=r"(d[0]), "=r"(d[1]), "=r"(d[2]), "=r"(d[3]) : "r"(a));
}
__device__ __forceinline__ void cpa16(void* dst, const void* src) {
    uint32_t d = (uint32_t)__cvta_generic_to_shared(dst);
    asm volatile("cp.async.ca.shared.global [%0], [%1], 16;\n" :: "r"(d), "l"(src));
}
#define CP_COMMIT() asm volatile("cp.async.commit_group;\n")
#define CP_WAIT(N)  asm volatile("cp.async.wait_group %0;\n" :: "n"(N))

// ==== GEMM: GBK=32 lean core + 2-stage cp.async pipeline (1 sync/iter) ====
#define GBM 128
#define GBN 64
#define GBK 32
#define APITCH 36   // 144B rows, 16B-aligned; ldsm phase r%8 distinct
#define BPITCH 72   // B fragment banks 8t+g all distinct
#define ABYTES (GBM * APITCH * 4)

__device__ __forceinline__
void gemm_pipe_core(const float* __restrict__ X, const float* __restrict__ W,
                    const float* __restrict__ aux, float* __restrict__ out, int mode)
{
    __shared__ float As[2][GBM * APITCH];   // 2 x 18.4 KB
    __shared__ float Bs[2][GBK * BPITCH];   // 2 x 9.2 KB

    const int row0 = blockIdx.y * GBM;
    const int col0 = blockIdx.x * GBN;
    const int tid  = threadIdx.x;
    const int lane = tid & 31, wid = tid >> 5;
    const int g = lane >> 2, t = lane & 3;
    const int warp_m = wid & 3, warp_n = wid >> 2;

    float acc[2][4][4];
#pragma unroll
    for (int mt = 0; mt < 2; ++mt)
#pragma unroll
        for (int nt = 0; nt < 4; ++nt)
#pragma unroll
            for (int e = 0; e < 4; ++e) acc[mt][nt][e] = 0.f;

    const uint32_t as_u = (uint32_t)__cvta_generic_to_shared(&As[0][0]);
    const uint32_t aoff = as_u +
        ((uint32_t)((warp_m * 32 + ((lane >> 3) & 1) * 8 + (lane & 7)) * APITCH
                    + (lane >> 4) * 4) << 2);
    const int c0 = warp_n * 32 + g;

    const int ar = tid >> 3, akq = (tid & 7) * 4;   // A: 128 rows x 32
    const int bk = tid >> 4, bnq = (tid & 15) * 4;  // B: 32 x 64

    auto issue = [&](int kt) {
        int s = kt & 1, k0 = kt * GBK;
#pragma unroll
        for (int i = 0; i < 4; ++i)
            cpa16(&As[s][(ar + i * 32) * APITCH + akq],
                  &X[(size_t)(row0 + ar + i * 32) * DMODEL + k0 + akq]);
#pragma unroll
        for (int i = 0; i < 2; ++i)
            cpa16(&Bs[s][(bk + i * 16) * BPITCH + bnq],
                  &W[(size_t)(k0 + bk + i * 16) * NCOLS + col0 + bnq]);
        CP_COMMIT();
    };
    issue(0);

    for (int kt = 0; kt < DMODEL / GBK; ++kt) {
        CP_WAIT(0);
        __syncthreads();
        if (kt + 1 < DMODEL / GBK) issue(kt + 1);

        const float* bs = Bs[kt & 1];
        const uint32_t abase = aoff + (uint32_t)((kt & 1) * ABYTES);
#pragma unroll
        for (int kc = 0; kc < GBK; kc += 8) {
            uint32_t af[2][4], bf[4][2];
#pragma unroll
            for (int mt = 0; mt < 2; ++mt) {
                ldsm4(af[mt], abase + (uint32_t)((mt * 16 * APITCH + kc) << 2));
                af[mt][0] = tf32u(af[mt][0]); af[mt][1] = tf32u(af[mt][1]);
                af[mt][2] = tf32u(af[mt][2]); af[mt][3] = tf32u(af[mt][3]);
            }
#pragma unroll
            for (int nt = 0; nt < 4; ++nt) {
                bf[nt][0] = tf32u(__float_as_uint(bs[(kc + t) * BPITCH + c0 + nt * 8]));
                bf[nt][1] = tf32u(__float_as_uint(bs[(kc + t + 4) * BPITCH + c0 + nt * 8]));
            }
#pragma unroll
            for (int mt = 0; mt < 2; ++mt)
#pragma unroll
                for (int nt = 0; nt < 4; ++nt)
                    mma8(acc[mt][nt],
                         af[mt][0], af[mt][1], af[mt][2], af[mt][3],
                         bf[nt][0], bf[nt][1]);
        }
    }

#pragma unroll
    for (int mt = 0; mt < 2; ++mt)
#pragma unroll
        for (int nt = 0; nt < 4; ++nt) {
            int rg0 = row0 + warp_m * 32 + mt * 16 + g;
            int cg  = col0 + warp_n * 32 + nt * 8 + 2 * t;
            int rr[4] = {rg0, rg0, rg0 + 8, rg0 + 8};
            int cc[4] = {cg, cg + 1, cg, cg + 1};
#pragma unroll
            for (int e = 0; e < 4; ++e) {
                int row = rr[e], col = cc[e];
                float v = acc[mt][nt][e];
                if (mode <= 2) {
                    if (mode == 0) v *= 0.125f;
                    int bb = row >> 11, l = row & (LSEQ - 1);
                    int hh = col >> 6,  cx = col & (DHEAD - 1);
                    float* dst = (mode == 0) ? g_qp : ((mode == 1) ? g_kp : g_vp);
                    dst[((((size_t)bb * NHEAD + hh) * LSEQ) + l) * DHEAD + cx] = tf32r(v);
                } else if (mode == 3) {
                    float xg = v + aux[col];
                    g_gate[(size_t)row * NCOLS + col] = 1.f / (1.f + __expf(-xg));
                } else {
                    out[(size_t)row * DMODEL + col] = v + aux[col];
                }
            }
        }
}

__global__ __launch_bounds__(256)
void proj4_kernel(const float* __restrict__ Q, const float* __restrict__ K,
                  const float* __restrict__ V,
                  const float* __restrict__ Wq, const float* __restrict__ Wk,
                  const float* __restrict__ Wv, const float* __restrict__ Wg,
                  const float* __restrict__ gbias)
{
    const int z = blockIdx.z;
    const float* X = (z == 1) ? K : ((z == 2) ? V : Q);
    const float* W = (z == 0) ? Wq : ((z == 1) ? Wk : ((z == 2) ? Wv : Wg));
    gemm_pipe_core(X, W, gbias, nullptr, z);
}

__global__ __launch_bounds__(256)
void oproj_kernel(const float* __restrict__ Xatt, const float* __restrict__ Wo,
                  const float* __restrict__ obias, float* __restrict__ out)
{
    gemm_pipe_core(Xatt, Wo, obias, out, 4);
}

// ===== Flash attention: BQ=256 (512 threads) — halves KV re-read traffic =====
#define BQ   256
#define NTHR 512
#define QP 68
#define KP 68
#define VP 72
#define ATTN_SMEM_FLOATS (BQ*QP + 2*64*KP + 2*64*VP)    // 35328
#define ATTN_SMEM_BYTES  (ATTN_SMEM_FLOATS * 4)         // 141312

__global__ __launch_bounds__(NTHR, 1)
void attn_kernel(const float* __restrict__ bias, const int* __restrict__ mask)
{
    extern __shared__ float sm[];
    float* q_s  = sm;                    // [256][68]
    float* k_sb = q_s + BQ * QP;         // 2 x [64][68]
    float* v_sb = k_sb + 2 * 64 * KP;    // 2 x [64][72]

    const int b = blockIdx.z, h = blockIdx.y;
    const int q0 = blockIdx.x * BQ;
    const int tid = threadIdx.x;
    const int lane = tid & 31, wid = tid >> 5;   // 16 warps
    const int g = lane >> 2, t = lane & 3;
    const int rw = wid * 16;
    const float L2E = 1.4426950408889634f;

    const float* kbase = g_kp + (((size_t)b * NHEAD + h) * LSEQ) * DHEAD;
    const float* vbase = g_vp + (((size_t)b * NHEAD + h) * LSEQ) * DHEAD;
    const float* qbase = g_qp + (((size_t)b * NHEAD + h) * LSEQ + q0) * DHEAD;

    // Q tile 256x64 -> smem (async, once)
#pragma unroll
    for (int i = 0; i < 8; ++i) {
        int idx = tid + i * NTHR;
        int r = idx >> 4, cq = (idx & 15) << 2;
        cpa16(&q_s[r * QP + cq], &qbase[(size_t)r * DHEAD + cq]);
    }
    CP_COMMIT();

    const int kvr = tid >> 3, kvc = (tid & 7) * 8;   // 64 rows x 8-float chunks
    auto issue = [&](int kt) {
        float* ks = k_sb + (kt & 1) * 64 * KP;
        float* vs = v_sb + (kt & 1) * 64 * VP;
        const float* kb = kbase + (size_t)kt * 64 * DHEAD;
        const float* vb = vbase + (size_t)kt * 64 * DHEAD;
        cpa16(&ks[kvr * KP + kvc],     &kb[(size_t)kvr * DHEAD + kvc]);
        cpa16(&ks[kvr * KP + kvc + 4], &kb[(size_t)kvr * DHEAD + kvc + 4]);
        cpa16(&vs[kvr * VP + kvc],     &vb[(size_t)kvr * DHEAD + kvc]);
        cpa16(&vs[kvr * VP + kvc + 4], &vb[(size_t)kvr * DHEAD + kvc + 4]);
        CP_COMMIT();
    };
    issue(0);

    const int i8 = lane & 7;
    const uint32_t smem_u = (uint32_t)__cvta_generic_to_shared(sm);
    const uint32_t qoff = smem_u +
        ((uint32_t)((rw + ((lane >> 3) & 1) * 8 + i8) * QP + (lane >> 4) * 4) << 2);
    const uint32_t koff = (uint32_t)(((lane >> 4) * 8 + i8) * KP
                                     + ((lane >> 3) & 1) * 4) << 2;
    const uint32_t k_u = smem_u + (uint32_t)(BQ * QP) * 4u;

    float acc[8][4];
#pragma unroll
    for (int nt = 0; nt < 8; ++nt)
#pragma unroll
        for (int e = 0; e < 4; ++e) acc[nt][e] = 0.f;
    float mA = -1e30f, mB = -1e30f, lA = 0.f, lB = 0.f;

    const size_t rowA = ((size_t)b * NHEAD + h) * LSEQ + q0 + rw + g;
    const size_t rowB = rowA + 8;
    const int srcA = (lane & ~3) | (t >> 1);
    const int srcB = srcA + 2;

    for (int kt = 0; kt < LSEQ / 64; ++kt) {
        CP_WAIT(0);
        __syncthreads();
        if (kt + 1 < LSEQ / 64) issue(kt + 1);

        const int k0 = kt * 64;

        float2 bA[8], bB[8];
        {
            const float* bAp = bias + rowA * (size_t)LSEQ + k0 + 2 * t;
            const float* bBp = bias + rowB * (size_t)LSEQ + k0 + 2 * t;
#pragma unroll
            for (int nt = 0; nt < 8; ++nt) {
                bA[nt] = __ldcs(reinterpret_cast<const float2*>(bAp + nt * 8));
                bB[nt] = __ldcs(reinterpret_cast<const float2*>(bBp + nt * 8));
            }
        }

        const uint32_t kb_u = k_u + (uint32_t)((kt & 1) * 64 * KP) * 4u + koff;
        const float* vs = v_sb + (kt & 1) * 64 * VP;

        float sacc[8][4];
#pragma unroll
        for (int nt = 0; nt < 8; ++nt)
#pragma unroll
            for (int e = 0; e < 4; ++e) sacc[nt][e] = 0.f;
#pragma unroll
        for (int j = 0; j < 8; ++j) {
            uint32_t af[4];
            ldsm4(af, qoff + (j << 5));
#pragma unroll
            for (int ntp = 0; ntp < 4; ++ntp) {
                uint32_t bf[4];
                ldsm4(bf, kb_u + (uint32_t)(ntp * 16 * KP) * 4u + (j << 5));
                mma8(sacc[2 * ntp],     af[0], af[1], af[2], af[3], bf[0], bf[1]);
                mma8(sacc[2 * ntp + 1], af[0], af[1], af[2], af[3], bf[2], bf[3]);
            }
        }

        uint32_t mbits = 0;
        {
            const int* mAp = mask + rowA * (size_t)LSEQ + k0 + 2 * t;
            const int* mBp = mask + rowB * (size_t)LSEQ + k0 + 2 * t;
#pragma unroll
            for (int nt = 0; nt < 8; ++nt) {
                int2 ma = __ldcs(reinterpret_cast<const int2*>(mAp + nt * 8));
                int2 mc = __ldcs(reinterpret_cast<const int2*>(mBp + nt * 8));
                sacc[nt][0] += bA[nt].x;  sacc[nt][1] += bA[nt].y;
                sacc[nt][2] += bB[nt].x;  sacc[nt][3] += bB[nt].y;
                mbits |= (ma.x ? 1u : 0u) << (nt * 4)
                       | (ma.y ? 1u : 0u) << (nt * 4 + 1)
                       | (mc.x ? 1u : 0u) << (nt * 4 + 2)
                       | (mc.y ? 1u : 0u) << (nt * 4 + 3);
            }
        }

        float mxA = -1e30f, mxB = -1e30f;
#pragma unroll
        for (int nt = 0; nt < 8; ++nt) {
            mxA = fmaxf(mxA, fmaxf(sacc[nt][0], sacc[nt][1]));
            mxB = fmaxf(mxB, fmaxf(sacc[nt][2], sacc[nt][3]));
        }
        mxA = fmaxf(mxA, __shfl_xor_sync(0xffffffffu, mxA, 1));
        mxA = fmaxf(mxA, __shfl_xor_sync(0xffffffffu, mxA, 2));
        mxB = fmaxf(mxB, __shfl_xor_sync(0xffffffffu, mxB, 1));
        mxB = fmaxf(mxB, __shfl_xor_sync(0xffffffffu, mxB, 2));
        float mnA = fmaxf(mA, mxA), mnB = fmaxf(mB, mxB);
        float alA = ex2((mA - mnA) * L2E), alB = ex2((mB - mnB) * L2E);
        mA = mnA; mB = mnB;

        float lsA = 0.f, lsB = 0.f;
#pragma unroll
        for (int nt = 0; nt < 8; ++nt) {
            float p0 = ex2((sacc[nt][0] - mnA) * L2E);
            float p1 = ex2((sacc[nt][1] - mnA) * L2E);
            float p2 = ex2((sacc[nt][2] - mnB) * L2E);
            float p3 = ex2((sacc[nt][3] - mnB) * L2E);
            lsA += p0 + p1;  lsB += p2 + p3;               // denom: ALL entries
            sacc[nt][0] = tf32r(((mbits >> (nt * 4    )) & 1u) ? p0 : 0.f);
            sacc[nt][1] = tf32r(((mbits >> (nt * 4 + 1)) & 1u) ? p1 : 0.f);
            sacc[nt][2] = tf32r(((mbits >> (nt * 4 + 2)) & 1u) ? p2 : 0.f);
            sacc[nt][3] = tf32r(((mbits >> (nt * 4 + 3)) & 1u) ? p3 : 0.f);
        }
        lsA += __shfl_xor_sync(0xffffffffu, lsA, 1);
        lsA += __shfl_xor_sync(0xffffffffu, lsA, 2);
        lsB += __shfl_xor_sync(0xffffffffu, lsB, 1);
        lsB += __shfl_xor_sync(0xffffffffu, lsB, 2);
        lA = lA * alA + lsA;  lB = lB * alB + lsB;

#pragma unroll
        for (int nt = 0; nt < 8; ++nt) {
            acc[nt][0] *= alA; acc[nt][1] *= alA;
            acc[nt][2] *= alB; acc[nt][3] *= alB;
        }
#pragma unroll
        for (int j = 0; j < 8; ++j) {
            float c0 = sacc[j][0], c1 = sacc[j][1], c2 = sacc[j][2], c3 = sacc[j][3];
            float v0 = __shfl_sync(0xffffffffu, c0, srcA);
            float v1 = __shfl_sync(0xffffffffu, c1, srcA);
            float v2 = __shfl_sync(0xffffffffu, c0, srcB);
            float v3 = __shfl_sync(0xffffffffu, c1, srcB);
            float w0 = __shfl_sync(0xffffffffu, c2, srcA);
            float w1 = __shfl_sync(0xffffffffu, c3, srcA);
            float w2 = __shfl_sync(0xffffffffu, c2, srcB);
            float w3 = __shfl_sync(0xffffffffu, c3, srcB);
            uint32_t pa0 = __float_as_uint((t & 1) ? v1 : v0);
            uint32_t pa1 = __float_as_uint((t & 1) ? w1 : w0);
            uint32_t pa2 = __float_as_uint((t & 1) ? v3 : v2);
            uint32_t pa3 = __float_as_uint((t & 1) ? w3 : w2);
#pragma unroll
            for (int nt = 0; nt < 8; ++nt) {
                uint32_t b0 = __float_as_uint(vs[(j * 8 + t) * VP + nt * 8 + g]);
                uint32_t b1 = __float_as_uint(vs[(j * 8 + t + 4) * VP + nt * 8 + g]);
                mma8(acc[nt], pa0, pa1, pa2, pa3, b0, b1);
            }
        }
    }

    float invA = 1.f / lA, invB = 1.f / lB;
    size_t gRowA = (size_t)b * LSEQ + q0 + rw + g;
    size_t gRowB = gRowA + 8;
#pragma unroll
    for (int nt = 0; nt < 8; ++nt) {
        size_t iA = gRowA * NCOLS + h * DHEAD + nt * 8 + 2 * t;
        size_t iB = gRowB * NCOLS + h * DHEAD + nt * 8 + 2 * t;
        float2 gA = *reinterpret_cast<const float2*>(&g_gate[iA]);
        float2 gB = *reinterpret_cast<const float2*>(&g_gate[iB]);
        float2 oA = { acc[nt][0] * invA * gA.x, acc[nt][1] * invA * gA.y };
        float2 oB = { acc[nt][2] * invB * gB.x, acc[nt][3] * invB * gB.y };
        *reinterpret_cast<float2*>(&g_att[iA]) = oA;
        *reinterpret_cast<float2*>(&g_att[iB]) = oB;
    }
}

// ===== launcher =====
extern "C" void kernel_launch(void* const* d_in, const int* in_sizes, int n_in,
                              void* d_out, int out_size)
{
    const float* Q    = (const float*)d_in[0];
    const float* K    = (const float*)d_in[1];
    const float* V    = (const float*)d_in[2];
    const float* bias = (const float*)d_in[3];
    const int*   mask = (const int*)d_in[4];
    const float* qw   = (const float*)d_in[5];
    const float* kw   = (const float*)d_in[6];
    const float* vw   = (const float*)d_in[7];
    const float* gw   = (const float*)d_in[8];
    const float* gb   = (const float*)d_in[9];
    const float* ow   = (const float*)d_in[10];
    const float* ob   = (const float*)d_in[11];
    float* out = (float*)d_out;

    static float* g_att_p = nullptr;
    if (!g_att_p) cudaGetSymbolAddress((void**)&g_att_p, g_att);

    cudaFuncSetAttribute(attn_kernel, cudaFuncAttributeMaxDynamicSharedMemorySize,
                         ATTN_SMEM_BYTES);

    dim3 gp(NCOLS / GBN, MROWS / GBM, 4);      // 16 x 32 x 4 = 2048 blocks
    proj4_kernel<<<gp, 256>>>(Q, K, V, qw, kw, vw, gw, gb);

    dim3 ga(LSEQ / BQ, NHEAD, NBATCH);         // 8 x 16 x 2 = 256 blocks
    attn_kernel<<<ga, NTHR, ATTN_SMEM_BYTES>>>(bias, mask);

    dim3 go(DMODEL / GBN, MROWS / GBM, 1);     // 16 x 32
    oproj_kernel<<<go, 256>>>(g_att_p, ow, ob, out);
}